// round 15
// baseline (speedup 1.0000x reference)
#include <cuda_runtime.h>
#include <cuda_bf16.h>
#include <math.h>
#include <stdint.h>

// Problem constants
#define BB 128
#define LL 200
#define D2 1024   // 2*SH
#define EH 512
#define AA 512
#define TT 3

#define NSPLIT 8  // split-K for small GEMMs
#define GM 2048   // unified gate-weight rows
#define GK 1536   // unified gate-weight cols

// -------- device scratch (allocation-free rule: __device__ globals) --------
__device__ float g_dproj[(size_t)BB * LL * AA];     // 52.4 MB  [m][a], m=b*L+l
__device__ float g_xT[1536 * BB];                   // rows 1024..1535 = h (fp32 state)
__device__ float g_part[NSPLIT * 2048 * BB];        // split-K partials [ks][row][b]
__device__ float g_qpart[NSPLIT * BB * AA];         // split-K partials for q
__device__ float g_q[BB * AA];                      // [b][a]
__device__ int   g_idx[BB * TT];
// pre-converted bf16 (h/l error split)
__device__ uint32_t g_Bh[512 * 512];                // wd high (bf16x2), 1 MB
__device__ uint32_t g_Bl[512 * 512];                // wd low
__device__ __nv_bfloat16 g_Wuh[(size_t)GM * GK];    // unified gate weights high
__device__ __nv_bfloat16 g_Wul[(size_t)GM * GK];    // low
__device__ __nv_bfloat16 g_xbh[(size_t)BB * GK];    // x [b][k] bf16 high (s_prev|h)
__device__ __nv_bfloat16 g_xbl[(size_t)BB * GK];    // low

// ---------------- small helpers ----------------
__device__ __forceinline__ float tanh_fast(float x) {
    float y;
    asm("tanh.approx.f32 %0, %1;" : "=f"(y) : "f"(x));
    return y;
}
__device__ __forceinline__ uint32_t smem_u32(const void* p) {
    uint32_t a;
    asm("{ .reg .u64 t; cvta.to.shared.u64 t, %1; cvt.u32.u64 %0, t; }" : "=r"(a) : "l"(p));
    return a;
}
__device__ __forceinline__ uint32_t pkbf(float lo, float hi) {
    uint32_t r;
    asm("cvt.rn.bf16x2.f32 %0, %1, %2;" : "=r"(r) : "f"(hi), "f"(lo));
    return r;
}
__device__ __forceinline__ float bf_lo(uint32_t v) { return __uint_as_float(v << 16); }
__device__ __forceinline__ float bf_hi(uint32_t v) { return __uint_as_float(v & 0xffff0000u); }

// ---------------- warp-level MMA plumbing (baseline PTX) ----------------
__device__ __forceinline__ void ldmx4(uint32_t* r, uint32_t addr) {
    asm volatile("ldmatrix.sync.aligned.m8n8.x4.shared.b16 {%0,%1,%2,%3}, [%4];"
                 : "=r"(r[0]), "=r"(r[1]), "=r"(r[2]), "=r"(r[3]) : "r"(addr));
}
__device__ __forceinline__ void mma_bf16(float* c, const uint32_t* a,
                                         uint32_t b0, uint32_t b1) {
    asm volatile("mma.sync.aligned.m16n8k16.row.col.f32.bf16.bf16.f32 "
                 "{%0,%1,%2,%3}, {%4,%5,%6,%7}, {%8,%9}, {%0,%1,%2,%3};"
                 : "+f"(c[0]), "+f"(c[1]), "+f"(c[2]), "+f"(c[3])
                 : "r"(a[0]), "r"(a[1]), "r"(a[2]), "r"(a[3]), "r"(b0), "r"(b1));
}
__device__ __forceinline__ void cp_async16(uint32_t dst, const void* src) {
    asm volatile("cp.async.cg.shared.global [%0], [%1], 16;" :: "r"(dst), "l"(src));
}
#define CP_COMMIT() asm volatile("cp.async.commit_group;" ::: "memory")
#define CP_WAIT(n)  asm volatile("cp.async.wait_group %0;" :: "n"(n) : "memory")

// -------------------------------------------------------------------------
// Unified gate weights -> bf16 h/l split with zero padding (runs once).
__global__ void k_cvtW(const float* __restrict__ w_ih, const float* __restrict__ w_hh) {
    const int j = blockIdx.x;            // 2048
    const int tid = threadIdx.x;         // 256
    for (int k = tid; k < GK; k += 256) {
        float v;
        if (j < 1024)       v = (k < 1024) ? w_ih[(size_t)j * 1024 + k]
                                           : w_hh[(size_t)j * 512 + (k - 1024)];
        else if (j < 1536)  v = (k < 1024) ? w_ih[(size_t)j * 1024 + k] : 0.f;
        else                v = (k >= 1024) ? w_hh[(size_t)(j - 512) * 512 + (k - 1024)] : 0.f;
        float h = __bfloat162float(__float2bfloat16_rn(v));
        g_Wuh[(size_t)j * GK + k] = __float2bfloat16_rn(v);
        g_Wul[(size_t)j * GK + k] = __float2bfloat16_rn(v - h);
    }
}

// -------------------------------------------------------------------------
// Pre-convert wd (512x1024 fp32) -> g_Bh/g_Bl bf16 h/l split (once)
__global__ void k_cvtB(const float* __restrict__ W) {
    const int row = blockIdx.x;          // 512
    const int tid = threadIdx.x;         // 256
    float4 v = reinterpret_cast<const float4*>(W + (size_t)row * 1024)[tid];
    uint32_t h0 = pkbf(v.x, v.y), h1 = pkbf(v.z, v.w);
    uint32_t l0 = pkbf(v.x - bf_lo(h0), v.y - bf_hi(h0));
    uint32_t l1 = pkbf(v.z - bf_lo(h1), v.w - bf_hi(h1));
    size_t base = (size_t)row * 512 + tid * 2;
    *reinterpret_cast<uint2*>(g_Bh + base) = make_uint2(h0, h1);
    *reinterpret_cast<uint2*>(g_Bl + base) = make_uint2(l0, l1);
}

// -------------------------------------------------------------------------
// h-rows only: transpose+convert xT[1024..1535][128] -> xb[b][1024+..] bf16 h/l
__global__ void k_cvth() {
    __shared__ float xs[16 * 128];
    const int k0 = 1024 + blockIdx.x * 16;   // 32 blocks
    const int tid = threadIdx.x;             // 256
    #pragma unroll
    for (int i = 0; i < 8; i++) {
        int t = tid + i * 256;
        xs[t] = g_xT[(size_t)(k0 + (t >> 7)) * BB + (t & 127)];
    }
    __syncthreads();
    const int b = tid >> 1, half = tid & 1;
    float v[8];
    #pragma unroll
    for (int kk = 0; kk < 8; kk++) v[kk] = xs[(half * 8 + kk) * 128 + b];
    uint32_t h[4], l[4];
    #pragma unroll
    for (int w = 0; w < 4; w++) {
        h[w] = pkbf(v[2 * w], v[2 * w + 1]);
        l[w] = pkbf(v[2 * w] - bf_lo(h[w]), v[2 * w + 1] - bf_hi(h[w]));
    }
    size_t off = (size_t)b * GK + k0 + half * 8;
    *reinterpret_cast<uint4*>(g_xbh + off) = make_uint4(h[0], h[1], h[2], h[3]);
    *reinterpret_cast<uint4*>(g_xbl + off) = make_uint4(l[0], l[1], l[2], l[3]);
}

// -------------------------------------------------------------------------
// h0 init (fp32 h state) + zero s_prev bf16 columns of xb
__global__ void k_init(const float* __restrict__ sent, const float* __restrict__ h0w,
                       const float* __restrict__ h0b) {
    int b = blockIdx.x;
    int tid = threadIdx.x;
    __shared__ float xs[512];
    const float* lb = sent + (size_t)b * LL * D2 + 512;
    for (int i = tid; i < 512; i += 256) xs[i] = lb[i];
    // zero s_prev rows of xb for this b (k < 1024)
    {
        size_t off = (size_t)b * GK + tid * 4;
        *reinterpret_cast<uint2*>(g_xbh + off) = make_uint2(0, 0);
        *reinterpret_cast<uint2*>(g_xbl + off) = make_uint2(0, 0);
    }
    __syncthreads();
    for (int e = tid; e < 512; e += 256) {
        const float4* wr = reinterpret_cast<const float4*>(h0w + (size_t)e * 512);
        float s = 0.f;
        #pragma unroll 8
        for (int i = 0; i < 128; i++) {
            float4 w = wr[i];
            float4 x = *reinterpret_cast<const float4*>(&xs[i * 4]);
            s = fmaf(w.x, x.x, s); s = fmaf(w.y, x.y, s);
            s = fmaf(w.z, x.z, s); s = fmaf(w.w, x.w, s);
        }
        g_xT[(size_t)(1024 + e) * BB + b] = tanhf(s + h0b[e]);
    }
}

// -------------------------------------------------------------------------
// d_proj (unchanged from R11/R14 win): bf16 3-product split on mma.sync
#define TPITCH 80
#define TSZ (128 * TPITCH)
#define BUFSZ (4 * TSZ)
#define SMEM_DP (2 * BUFSZ)

__global__ __launch_bounds__(256, 2) void k_dproj(const float* __restrict__ Ag,
                                                  const float* __restrict__ bd,
                                                  float* __restrict__ C) {
    extern __shared__ char smdp[];
    const int tid = threadIdx.x;
    const int lane = tid & 31, warp = tid >> 5;
    const int wm = warp >> 1, wn = warp & 1;
    const int n0 = blockIdx.x * 128, m0 = blockIdx.y * 128;
    const uint32_t sb = smem_u32(smdp);

    float acc[2][8][4];
    #pragma unroll
    for (int i = 0; i < 2; i++)
        #pragma unroll
        for (int j = 0; j < 8; j++)
            #pragma unroll
            for (int k = 0; k < 4; k++) acc[i][j][k] = 0.f;

    const uint32_t a_rel = (uint32_t)(wm * 32 + (lane & 15)) * TPITCH + ((lane >> 4) * 8) * 2;
    const uint32_t b_rel = (uint32_t)(wn * 64 + (lane & 15)) * TPITCH + ((lane >> 4) * 8) * 2;

    const int srow = tid & 127, shalf = tid >> 7;
    const float4* Arow = reinterpret_cast<const float4*>(Ag + (size_t)(m0 + srow) * 1024);
    const uint32_t st_off = (uint32_t)srow * TPITCH + (uint32_t)shalf * 32;

    float4 ra[4];
    auto stageA = [&](int c) {
        const float4* a4 = Arow + c * 8 + shalf * 4;
        #pragma unroll
        for (int i = 0; i < 4; i++) ra[i] = a4[i];
    };
    auto convertA = [&](uint32_t base) {
        char* sbase = smdp + base;
        #pragma unroll
        for (int i = 0; i < 4; i++) {
            float4 v = ra[i];
            uint32_t h0 = pkbf(v.x, v.y), h1 = pkbf(v.z, v.w);
            uint32_t l0 = pkbf(v.x - bf_lo(h0), v.y - bf_hi(h0));
            uint32_t l1 = pkbf(v.z - bf_lo(h1), v.w - bf_hi(h1));
            *reinterpret_cast<uint2*>(sbase + st_off + i * 8) = make_uint2(h0, h1);
            *reinterpret_cast<uint2*>(sbase + TSZ + st_off + i * 8) = make_uint2(l0, l1);
        }
    };
    auto loadB = [&](int c, uint32_t base) {
        const int kcu = c * 16;
        #pragma unroll
        for (int i = 0; i < 4; i++) {
            const int t = tid + i * 256;
            const int tile = t >> 9;
            const int tt = t & 511;
            const int row = tt >> 2, q = tt & 3;
            const uint32_t dst = sb + base + (uint32_t)(2 + tile) * TSZ
                                 + (uint32_t)row * TPITCH + (uint32_t)q * 16;
            const uint32_t* src = (tile ? g_Bl : g_Bh)
                                  + (size_t)(n0 + row) * 512 + kcu + q * 4;
            cp_async16(dst, src);
        }
    };

    stageA(0);
    loadB(0, 0);
    CP_COMMIT();
    convertA(0);
    stageA(1);
    CP_WAIT(0);
    __syncthreads();

    for (int c = 0; c < 32; c++) {
        const uint32_t base = (uint32_t)(c & 1) * BUFSZ;
        const uint32_t nbase = (uint32_t)((c + 1) & 1) * BUFSZ;
        if (c < 31) {
            loadB(c + 1, nbase);
            CP_COMMIT();
        }
        #pragma unroll
        for (int kk = 0; kk < 2; kk++) {
            uint32_t ah[2][4], al[2][4], bf[4];
            #pragma unroll
            for (int mi = 0; mi < 2; mi++)
                ldmx4(ah[mi], sb + base + a_rel + (uint32_t)(mi * 16) * TPITCH + kk * 32);
            #pragma unroll
            for (int mi = 0; mi < 2; mi++)
                ldmx4(al[mi], sb + base + TSZ + a_rel + (uint32_t)(mi * 16) * TPITCH + kk * 32);
            #pragma unroll
            for (int np = 0; np < 4; np++) {
                ldmx4(bf, sb + base + 2 * TSZ + b_rel + (uint32_t)(np * 16) * TPITCH + kk * 32);
                #pragma unroll
                for (int mi = 0; mi < 2; mi++)
                    #pragma unroll
                    for (int nb = 0; nb < 2; nb++)
                        mma_bf16(acc[mi][np * 2 + nb], ah[mi], bf[nb], bf[nb + 2]);
                #pragma unroll
                for (int mi = 0; mi < 2; mi++)
                    #pragma unroll
                    for (int nb = 0; nb < 2; nb++)
                        mma_bf16(acc[mi][np * 2 + nb], al[mi], bf[nb], bf[nb + 2]);
            }
            #pragma unroll
            for (int np = 0; np < 4; np++) {
                ldmx4(bf, sb + base + 3 * TSZ + b_rel + (uint32_t)(np * 16) * TPITCH + kk * 32);
                #pragma unroll
                for (int mi = 0; mi < 2; mi++)
                    #pragma unroll
                    for (int nb = 0; nb < 2; nb++)
                        mma_bf16(acc[mi][np * 2 + nb], ah[mi], bf[nb], bf[nb + 2]);
            }
        }
        if (c < 31) {
            convertA(nbase);
            if (c < 30) stageA(c + 2);
            CP_WAIT(0);
        }
        __syncthreads();
    }

    #pragma unroll
    for (int mi = 0; mi < 2; mi++) {
        const int r = m0 + wm * 32 + mi * 16 + (lane >> 2);
        #pragma unroll
        for (int ni = 0; ni < 8; ni++) {
            const int cc = n0 + wn * 64 + ni * 8 + (lane & 3) * 2;
            const float b0 = bd[cc], b1 = bd[cc + 1];
            float2 v0 = make_float2(acc[mi][ni][0] + b0, acc[mi][ni][1] + b1);
            float2 v1 = make_float2(acc[mi][ni][2] + b0, acc[mi][ni][3] + b1);
            *reinterpret_cast<float2*>(C + (size_t)r * 512 + cc) = v0;
            *reinterpret_cast<float2*>(C + (size_t)(r + 8) * 512 + cc) = v1;
        }
    }
}

// -------------------------------------------------------------------------
// Gates via mma (unchanged from R14 win). GTP=80 (16B-aligned rows).
#define GTP 80
#define GTSZ (128 * GTP)
#define GBUF (4 * GTSZ)
#define SMEM_G (2 * GBUF)   // 81920 B

__global__ __launch_bounds__(256, 2) void k_gates_mma() {
    extern __shared__ char smg[];
    const int tid = threadIdx.x;
    const int lane = tid & 31, warp = tid >> 5;
    const int wm = warp >> 1, wn = warp & 1;
    const int j0 = blockIdx.x * 128;
    const int ks = blockIdx.y;
    const uint32_t sb = smem_u32(smg);

    float acc[2][8][4];
    #pragma unroll
    for (int i = 0; i < 2; i++)
        #pragma unroll
        for (int j = 0; j < 8; j++)
            #pragma unroll
            for (int k = 0; k < 4; k++) acc[i][j][k] = 0.f;

    const uint32_t a_rel = (uint32_t)(wm * 32 + (lane & 15)) * GTP + ((lane >> 4) * 8) * 2;
    const uint32_t b_rel = (uint32_t)(wn * 64 + (lane & 15)) * GTP + ((lane >> 4) * 8) * 2;
    const int koff = ks * 192;

    auto loadT = [&](int c, uint32_t base) {
        const int kc = koff + c * 32;
        #pragma unroll
        for (int i = 0; i < 8; i++) {
            const int t = tid + i * 256;
            const int tile = t >> 9;             // 0 Wh, 1 Wl, 2 xh, 3 xl
            const int tt = t & 511;
            const int row = tt >> 2, q = tt & 3;
            const uint32_t dst = sb + base + (uint32_t)tile * GTSZ
                                 + (uint32_t)row * GTP + (uint32_t)q * 16;
            const __nv_bfloat16* src;
            if (tile == 0)      src = g_Wuh + (size_t)(j0 + row) * GK + kc + q * 8;
            else if (tile == 1) src = g_Wul + (size_t)(j0 + row) * GK + kc + q * 8;
            else if (tile == 2) src = g_xbh + (size_t)row * GK + kc + q * 8;
            else                src = g_xbl + (size_t)row * GK + kc + q * 8;
            cp_async16(dst, src);
        }
    };

    loadT(0, 0);
    CP_COMMIT();
    CP_WAIT(0);
    __syncthreads();

    for (int c = 0; c < 6; c++) {
        const uint32_t base = (uint32_t)(c & 1) * GBUF;
        const uint32_t nbase = (uint32_t)((c + 1) & 1) * GBUF;
        if (c < 5) {
            loadT(c + 1, nbase);
            CP_COMMIT();
        }
        #pragma unroll
        for (int kk = 0; kk < 2; kk++) {
            uint32_t ah[2][4], al[2][4], bf[4];
            #pragma unroll
            for (int mi = 0; mi < 2; mi++)
                ldmx4(ah[mi], sb + base + a_rel + (uint32_t)(mi * 16) * GTP + kk * 32);
            #pragma unroll
            for (int mi = 0; mi < 2; mi++)
                ldmx4(al[mi], sb + base + GTSZ + a_rel + (uint32_t)(mi * 16) * GTP + kk * 32);
            #pragma unroll
            for (int np = 0; np < 4; np++) {
                ldmx4(bf, sb + base + 2 * GTSZ + b_rel + (uint32_t)(np * 16) * GTP + kk * 32);
                #pragma unroll
                for (int mi = 0; mi < 2; mi++)
                    #pragma unroll
                    for (int nb = 0; nb < 2; nb++)
                        mma_bf16(acc[mi][np * 2 + nb], ah[mi], bf[nb], bf[nb + 2]);
                #pragma unroll
                for (int mi = 0; mi < 2; mi++)
                    #pragma unroll
                    for (int nb = 0; nb < 2; nb++)
                        mma_bf16(acc[mi][np * 2 + nb], al[mi], bf[nb], bf[nb + 2]);
            }
            #pragma unroll
            for (int np = 0; np < 4; np++) {
                ldmx4(bf, sb + base + 3 * GTSZ + b_rel + (uint32_t)(np * 16) * GTP + kk * 32);
                #pragma unroll
                for (int mi = 0; mi < 2; mi++)
                    #pragma unroll
                    for (int nb = 0; nb < 2; nb++)
                        mma_bf16(acc[mi][np * 2 + nb], ah[mi], bf[nb], bf[nb + 2]);
            }
        }
        if (c < 5) CP_WAIT(0);
        __syncthreads();
    }

    float* P = g_part + (size_t)ks * 2048 * BB;
    #pragma unroll
    for (int mi = 0; mi < 2; mi++) {
        const int r = j0 + wm * 32 + mi * 16 + (lane >> 2);
        #pragma unroll
        for (int ni = 0; ni < 8; ni++) {
            const int cc = wn * 64 + ni * 8 + (lane & 3) * 2;
            *reinterpret_cast<float2*>(P + (size_t)r * BB + cc) =
                make_float2(acc[mi][ni][0], acc[mi][ni][1]);
            *reinterpret_cast<float2*>(P + (size_t)(r + 8) * BB + cc) =
                make_float2(acc[mi][ni][2], acc[mi][ni][3]);
        }
    }
}

// -------------------------------------------------------------------------
// Small tall-skinny GEMM body (fp32) — used by k_q
template <int JPT>
__device__ __forceinline__ void gemm_cols(const float* __restrict__ W, int K,
                                          int kc0, int kcnt,
                                          const float* __restrict__ xcol,
                                          int b, int jj, float acc[JPT], float* Ws) {
    const int JT = 2 * JPT;
    #pragma unroll
    for (int u = 0; u < JPT; u++) acc[u] = 0.f;
    for (int kc = kc0; kc < kc0 + kcnt; kc += 64) {
        __syncthreads();
        for (int i = threadIdx.x; i < JT * 16; i += blockDim.x) {
            int j = i >> 4, kq = i & 15;
            *reinterpret_cast<float4*>(Ws + j * 64 + kq * 4) =
                *reinterpret_cast<const float4*>(W + (size_t)j * K + kc + kq * 4);
        }
        __syncthreads();
        #pragma unroll 4
        for (int k = 0; k < 64; k += 4) {
            float x0 = xcol[(size_t)(kc + k + 0) * BB + b];
            float x1 = xcol[(size_t)(kc + k + 1) * BB + b];
            float x2 = xcol[(size_t)(kc + k + 2) * BB + b];
            float x3 = xcol[(size_t)(kc + k + 3) * BB + b];
            #pragma unroll
            for (int u = 0; u < JPT; u++) {
                float4 w = *reinterpret_cast<const float4*>(Ws + (jj * JPT + u) * 64 + k);
                acc[u] = fmaf(w.x, x0, acc[u]);
                acc[u] = fmaf(w.y, x1, acc[u]);
                acc[u] = fmaf(w.z, x2, acc[u]);
                acc[u] = fmaf(w.w, x3, acc[u]);
            }
        }
    }
}

// GRU combine: sum partials + biases, h' = (1-z)*n + z*h (fp32 state in xT)
__global__ void k_comb(const float* __restrict__ b_ih, const float* __restrict__ b_hh) {
    int gid = blockIdx.x * blockDim.x + threadIdx.x;
    if (gid >= BB * EH) return;
    int b = gid & 127, e = gid >> 7;
    float rg = b_ih[e] + b_hh[e];
    float zg = b_ih[512 + e] + b_hh[512 + e];
    float xn = b_ih[1024 + e];
    float hn = b_hh[1024 + e];
    #pragma unroll
    for (int ks = 0; ks < NSPLIT; ks++) {
        const float* P = g_part + (size_t)ks * 2048 * BB;
        rg += P[(size_t)e * BB + b];
        zg += P[(size_t)(512 + e) * BB + b];
        xn += P[(size_t)(1024 + e) * BB + b];
        hn += P[(size_t)(1536 + e) * BB + b];
    }
    float hv = g_xT[(size_t)(1024 + e) * BB + b];
    float r = 1.f / (1.f + expf(-rg));
    float z = 1.f / (1.f + expf(-zg));
    float n = tanhf(fmaf(r, hn, xn));
    g_xT[(size_t)(1024 + e) * BB + b] = fmaf(1.f - z, n, z * hv);
}

// q partials: grid (64 jblocks, NSPLIT), K=512
__global__ __launch_bounds__(256) void k_q(const float* __restrict__ wq) {
    __shared__ float Ws[8 * 64];
    const int j0 = blockIdx.x * 8;
    const int ks = blockIdx.y;
    const int tid = threadIdx.x;
    const int b = tid & 127, jj = tid >> 7;
    const int kper = 512 / NSPLIT;
    float acc[4];
    gemm_cols<4>(wq + (size_t)j0 * 512, 512, ks * kper, kper,
                 g_xT + (size_t)1024 * BB, b, jj, acc, Ws);
    float* P = g_qpart + (size_t)ks * BB * AA;
    #pragma unroll
    for (int u = 0; u < 4; u++) {
        int jl = jj * 4 + u;
        P[(size_t)b * 512 + j0 + jl] = acc[u];
    }
}

__global__ void k_qsum(const float* __restrict__ bq) {
    int gid = blockIdx.x * blockDim.x + threadIdx.x;
    if (gid >= BB * AA) return;
    int a = gid & 511;
    float s = bq[a];
    #pragma unroll
    for (int ks = 0; ks < NSPLIT; ks++) s += g_qpart[(size_t)ks * BB * AA + gid];
    g_q[gid] = s;
}

// -------------------------------------------------------------------------
// Fused score + argmax + gather: one block per b.
// score[b,l] = ws . tanh(q[b] + d_proj[b,l]) + bs, masked; argmax (first-max);
// gather selected sentence -> bf16 h/l s_prev columns of xb.
__global__ __launch_bounds__(256) void k_select(const float* __restrict__ sent,
                                                const float* __restrict__ ws,
                                                const float* __restrict__ bsp,
                                                int t, float* __restrict__ outs,
                                                float* __restrict__ out_sel) {
    const int b = blockIdx.x;
    const int tid = threadIdx.x;
    const int w = tid >> 5, lane = tid & 31;
    __shared__ float sc[200];
    __shared__ float sv[256];
    __shared__ int si[256];

    // preload q[b] and ws into registers (lane-partitioned)
    const float4* qv4 = reinterpret_cast<const float4*>(g_q + (size_t)b * AA);
    const float4* wv4 = reinterpret_cast<const float4*>(ws);
    float4 qr[4], wr[4];
    #pragma unroll
    for (int i = 0; i < 4; i++) { qr[i] = qv4[lane + 32 * i]; wr[i] = wv4[lane + 32 * i]; }

    float* orow = outs + ((size_t)b * TT + t) * LL;
    for (int i = 0; i < 25; i++) {
        const int l = i * 8 + w;
        const float4* dp = reinterpret_cast<const float4*>(
            g_dproj + (size_t)(b * LL + l) * AA);
        float acc = 0.f;
        #pragma unroll
        for (int j = 0; j < 4; j++) {
            float4 d = dp[lane + 32 * j];
            acc = fmaf(wr[j].x, tanh_fast(d.x + qr[j].x), acc);
            acc = fmaf(wr[j].y, tanh_fast(d.y + qr[j].y), acc);
            acc = fmaf(wr[j].z, tanh_fast(d.z + qr[j].z), acc);
            acc = fmaf(wr[j].w, tanh_fast(d.w + qr[j].w), acc);
        }
        #pragma unroll
        for (int off = 16; off; off >>= 1) acc += __shfl_xor_sync(0xffffffffu, acc, off);
        if (lane == 0) {
            float s = acc + bsp[0];
            for (int tt = 0; tt < t; tt++)
                if (g_idx[b * TT + tt] == l) s = -1000000.0f;
            sc[l] = s;
            orow[l] = s;
        }
    }
    __syncthreads();

    // argmax over sc[200], first-max tie break
    float bv = -3.0e38f; int bi = 0;
    for (int l = tid; l < LL; l += 256) {
        float v = sc[l];
        if (v > bv) { bv = v; bi = l; }
    }
    sv[tid] = bv; si[tid] = bi;
    __syncthreads();
    for (int s = 128; s > 0; s >>= 1) {
        if (tid < s) {
            if (sv[tid + s] > sv[tid] || (sv[tid + s] == sv[tid] && si[tid + s] < si[tid])) {
                sv[tid] = sv[tid + s]; si[tid] = si[tid + s];
            }
        }
        __syncthreads();
    }
    const int idx = si[0];
    if (tid == 0) { g_idx[b * TT + t] = idx; out_sel[b * TT + t] = (float)idx; }

    // gather selected sentence -> bf16 h/l s_prev columns (k < 1024)
    const float* srow = sent + ((size_t)(b * LL) + idx) * D2;
    {
        const int k = tid * 4;
        float4 v = *reinterpret_cast<const float4*>(srow + k);
        uint32_t h0 = pkbf(v.x, v.y), h1 = pkbf(v.z, v.w);
        uint32_t l0 = pkbf(v.x - bf_lo(h0), v.y - bf_hi(h0));
        uint32_t l1 = pkbf(v.z - bf_lo(h1), v.w - bf_hi(h1));
        size_t off = (size_t)b * GK + k;
        *reinterpret_cast<uint2*>(g_xbh + off) = make_uint2(h0, h1);
        *reinterpret_cast<uint2*>(g_xbl + off) = make_uint2(l0, l1);
    }
}

// -------------------------------------------------------------------------
extern "C" void kernel_launch(void* const* d_in, const int* in_sizes, int n_in,
                              void* d_out, int out_size) {
    const float* sent = (const float*)d_in[0];
    const float* h0w  = (const float*)d_in[1];
    const float* h0b  = (const float*)d_in[2];
    const float* w_ih = (const float*)d_in[3];
    const float* w_hh = (const float*)d_in[4];
    const float* b_ih = (const float*)d_in[5];
    const float* b_hh = (const float*)d_in[6];
    const float* wq   = (const float*)d_in[7];
    const float* bq   = (const float*)d_in[8];
    const float* wd   = (const float*)d_in[9];
    const float* bd   = (const float*)d_in[10];
    const float* ws   = (const float*)d_in[11];
    const float* bsp  = (const float*)d_in[12];
    (void)in_sizes; (void)n_in; (void)out_size;

    float* out = (float*)d_out;
    float* out_scores = out;
    float* out_sel = out + (size_t)BB * TT * LL;

    float* dproj_ptr = nullptr;
    cudaGetSymbolAddress((void**)&dproj_ptr, g_dproj);

    cudaFuncSetAttribute(k_dproj, cudaFuncAttributeMaxDynamicSharedMemorySize, SMEM_DP);
    cudaFuncSetAttribute(k_gates_mma, cudaFuncAttributeMaxDynamicSharedMemorySize, SMEM_G);

    k_cvtW<<<GM, 256>>>(w_ih, w_hh);
    k_cvtB<<<512, 256>>>(wd);
    k_init<<<BB, 256>>>(sent, h0w, h0b);
    k_cvth<<<32, 256>>>();                       // h0 -> bf16 xb
    k_dproj<<<dim3(4, 200), 256, SMEM_DP>>>(sent, bd, dproj_ptr);
    for (int t = 0; t < TT; t++) {
        k_gates_mma<<<dim3(16, 8), 256, SMEM_G>>>();
        k_comb<<<256, 256>>>(b_ih, b_hh);
        k_cvth<<<32, 256>>>();                   // h' -> bf16 xb
        k_q<<<dim3(64, NSPLIT), 256>>>(wq);
        k_qsum<<<256, 256>>>(bq);
        k_select<<<BB, 256>>>(sent, ws, bsp, t, out_scores, out_sel);
    }
}

// round 16
// speedup vs baseline: 1.0969x; 1.0969x over previous
#include <cuda_runtime.h>
#include <cuda_bf16.h>
#include <math.h>
#include <stdint.h>

// Problem constants
#define BB 128
#define LL 200
#define D2 1024   // 2*SH
#define EH 512
#define AA 512
#define TT 3

#define NSPLIT 8  // split-K for small GEMMs
#define GM 2048   // unified gate-weight rows
#define GK 1536   // unified gate-weight cols

// -------- device scratch (allocation-free rule: __device__ globals) --------
__device__ float g_dproj[(size_t)BB * LL * AA];     // 52.4 MB  [m][a], m=b*L+l
__device__ float g_xT[1536 * BB];                   // rows 1024..1535 = h (fp32 state)
__device__ float g_part[NSPLIT * 2048 * BB];        // split-K partials [ks][row][b]
__device__ float g_qpart[NSPLIT * BB * AA];         // split-K partials for q
__device__ float g_q[BB * AA];                      // [b][a]
__device__ int   g_idx[BB * TT];
// pre-converted bf16 (h/l error split)
__device__ uint32_t g_Bh[512 * 512];                // wd high (bf16x2), 1 MB
__device__ uint32_t g_Bl[512 * 512];                // wd low
__device__ __nv_bfloat16 g_Wuh[(size_t)GM * GK];    // unified gate weights high
__device__ __nv_bfloat16 g_Wul[(size_t)GM * GK];    // low
__device__ __nv_bfloat16 g_xbh[(size_t)BB * GK];    // x [b][k] bf16 high (s_prev|h)
__device__ __nv_bfloat16 g_xbl[(size_t)BB * GK];    // low

// ---------------- small helpers ----------------
__device__ __forceinline__ float tanh_fast(float x) {
    float y;
    asm("tanh.approx.f32 %0, %1;" : "=f"(y) : "f"(x));
    return y;
}
__device__ __forceinline__ uint32_t smem_u32(const void* p) {
    uint32_t a;
    asm("{ .reg .u64 t; cvta.to.shared.u64 t, %1; cvt.u32.u64 %0, t; }" : "=r"(a) : "l"(p));
    return a;
}
__device__ __forceinline__ uint32_t pkbf(float lo, float hi) {
    uint32_t r;
    asm("cvt.rn.bf16x2.f32 %0, %1, %2;" : "=r"(r) : "f"(hi), "f"(lo));
    return r;
}
__device__ __forceinline__ float bf_lo(uint32_t v) { return __uint_as_float(v << 16); }
__device__ __forceinline__ float bf_hi(uint32_t v) { return __uint_as_float(v & 0xffff0000u); }

// ---------------- warp-level MMA plumbing (baseline PTX) ----------------
__device__ __forceinline__ void ldmx4(uint32_t* r, uint32_t addr) {
    asm volatile("ldmatrix.sync.aligned.m8n8.x4.shared.b16 {%0,%1,%2,%3}, [%4];"
                 : "=r"(r[0]), "=r"(r[1]), "=r"(r[2]), "=r"(r[3]) : "r"(addr));
}
__device__ __forceinline__ void mma_bf16(float* c, const uint32_t* a,
                                         uint32_t b0, uint32_t b1) {
    asm volatile("mma.sync.aligned.m16n8k16.row.col.f32.bf16.bf16.f32 "
                 "{%0,%1,%2,%3}, {%4,%5,%6,%7}, {%8,%9}, {%0,%1,%2,%3};"
                 : "+f"(c[0]), "+f"(c[1]), "+f"(c[2]), "+f"(c[3])
                 : "r"(a[0]), "r"(a[1]), "r"(a[2]), "r"(a[3]), "r"(b0), "r"(b1));
}
__device__ __forceinline__ void cp_async16(uint32_t dst, const void* src) {
    asm volatile("cp.async.cg.shared.global [%0], [%1], 16;" :: "r"(dst), "l"(src));
}
#define CP_COMMIT() asm volatile("cp.async.commit_group;" ::: "memory")
#define CP_WAIT(n)  asm volatile("cp.async.wait_group %0;" :: "n"(n) : "memory")

// -------------------------------------------------------------------------
// Unified gate weights -> bf16 h/l split with zero padding (runs once).
__global__ void k_cvtW(const float* __restrict__ w_ih, const float* __restrict__ w_hh) {
    const int j = blockIdx.x;            // 2048
    const int tid = threadIdx.x;         // 256
    for (int k = tid; k < GK; k += 256) {
        float v;
        if (j < 1024)       v = (k < 1024) ? w_ih[(size_t)j * 1024 + k]
                                           : w_hh[(size_t)j * 512 + (k - 1024)];
        else if (j < 1536)  v = (k < 1024) ? w_ih[(size_t)j * 1024 + k] : 0.f;
        else                v = (k >= 1024) ? w_hh[(size_t)(j - 512) * 512 + (k - 1024)] : 0.f;
        float h = __bfloat162float(__float2bfloat16_rn(v));
        g_Wuh[(size_t)j * GK + k] = __float2bfloat16_rn(v);
        g_Wul[(size_t)j * GK + k] = __float2bfloat16_rn(v - h);
    }
}

// -------------------------------------------------------------------------
// Pre-convert wd (512x1024 fp32) -> g_Bh/g_Bl bf16 h/l split (once)
__global__ void k_cvtB(const float* __restrict__ W) {
    const int row = blockIdx.x;          // 512
    const int tid = threadIdx.x;         // 256
    float4 v = reinterpret_cast<const float4*>(W + (size_t)row * 1024)[tid];
    uint32_t h0 = pkbf(v.x, v.y), h1 = pkbf(v.z, v.w);
    uint32_t l0 = pkbf(v.x - bf_lo(h0), v.y - bf_hi(h0));
    uint32_t l1 = pkbf(v.z - bf_lo(h1), v.w - bf_hi(h1));
    size_t base = (size_t)row * 512 + tid * 2;
    *reinterpret_cast<uint2*>(g_Bh + base) = make_uint2(h0, h1);
    *reinterpret_cast<uint2*>(g_Bl + base) = make_uint2(l0, l1);
}

// -------------------------------------------------------------------------
// h0 init: fp32 h state + bf16 h/l of h0 + zero bf16 s_prev rows
__global__ void k_init(const float* __restrict__ sent, const float* __restrict__ h0w,
                       const float* __restrict__ h0b) {
    int b = blockIdx.x;
    int tid = threadIdx.x;
    __shared__ float xs[512];
    const float* lb = sent + (size_t)b * LL * D2 + 512;
    for (int i = tid; i < 512; i += 256) xs[i] = lb[i];
    // zero s_prev rows of xb for this b (k < 1024): 4 bf16 per thread per array
    {
        size_t off = (size_t)b * GK + tid * 4;
        *reinterpret_cast<uint2*>(g_xbh + off) = make_uint2(0, 0);
        *reinterpret_cast<uint2*>(g_xbl + off) = make_uint2(0, 0);
    }
    __syncthreads();
    for (int e = tid; e < 512; e += 256) {
        const float4* wr = reinterpret_cast<const float4*>(h0w + (size_t)e * 512);
        float s = 0.f;
        #pragma unroll 8
        for (int i = 0; i < 128; i++) {
            float4 w = wr[i];
            float4 x = *reinterpret_cast<const float4*>(&xs[i * 4]);
            s = fmaf(w.x, x.x, s); s = fmaf(w.y, x.y, s);
            s = fmaf(w.z, x.z, s); s = fmaf(w.w, x.w, s);
        }
        float hv = tanhf(s + h0b[e]);
        g_xT[(size_t)(1024 + e) * BB + b] = hv;
        __nv_bfloat16 hb = __float2bfloat16_rn(hv);
        g_xbh[(size_t)b * GK + 1024 + e] = hb;
        g_xbl[(size_t)b * GK + 1024 + e] =
            __float2bfloat16_rn(hv - __bfloat162float(hb));
    }
}

// -------------------------------------------------------------------------
// d_proj (unchanged from R11/R14 win): bf16 3-product split on mma.sync
#define TPITCH 80
#define TSZ (128 * TPITCH)
#define BUFSZ (4 * TSZ)
#define SMEM_DP (2 * BUFSZ)

__global__ __launch_bounds__(256, 2) void k_dproj(const float* __restrict__ Ag,
                                                  const float* __restrict__ bd,
                                                  float* __restrict__ C) {
    extern __shared__ char smdp[];
    const int tid = threadIdx.x;
    const int lane = tid & 31, warp = tid >> 5;
    const int wm = warp >> 1, wn = warp & 1;
    const int n0 = blockIdx.x * 128, m0 = blockIdx.y * 128;
    const uint32_t sb = smem_u32(smdp);

    float acc[2][8][4];
    #pragma unroll
    for (int i = 0; i < 2; i++)
        #pragma unroll
        for (int j = 0; j < 8; j++)
            #pragma unroll
            for (int k = 0; k < 4; k++) acc[i][j][k] = 0.f;

    const uint32_t a_rel = (uint32_t)(wm * 32 + (lane & 15)) * TPITCH + ((lane >> 4) * 8) * 2;
    const uint32_t b_rel = (uint32_t)(wn * 64 + (lane & 15)) * TPITCH + ((lane >> 4) * 8) * 2;

    const int srow = tid & 127, shalf = tid >> 7;
    const float4* Arow = reinterpret_cast<const float4*>(Ag + (size_t)(m0 + srow) * 1024);
    const uint32_t st_off = (uint32_t)srow * TPITCH + (uint32_t)shalf * 32;

    float4 ra[4];
    auto stageA = [&](int c) {
        const float4* a4 = Arow + c * 8 + shalf * 4;
        #pragma unroll
        for (int i = 0; i < 4; i++) ra[i] = a4[i];
    };
    auto convertA = [&](uint32_t base) {
        char* sbase = smdp + base;
        #pragma unroll
        for (int i = 0; i < 4; i++) {
            float4 v = ra[i];
            uint32_t h0 = pkbf(v.x, v.y), h1 = pkbf(v.z, v.w);
            uint32_t l0 = pkbf(v.x - bf_lo(h0), v.y - bf_hi(h0));
            uint32_t l1 = pkbf(v.z - bf_lo(h1), v.w - bf_hi(h1));
            *reinterpret_cast<uint2*>(sbase + st_off + i * 8) = make_uint2(h0, h1);
            *reinterpret_cast<uint2*>(sbase + TSZ + st_off + i * 8) = make_uint2(l0, l1);
        }
    };
    auto loadB = [&](int c, uint32_t base) {
        const int kcu = c * 16;
        #pragma unroll
        for (int i = 0; i < 4; i++) {
            const int t = tid + i * 256;
            const int tile = t >> 9;
            const int tt = t & 511;
            const int row = tt >> 2, q = tt & 3;
            const uint32_t dst = sb + base + (uint32_t)(2 + tile) * TSZ
                                 + (uint32_t)row * TPITCH + (uint32_t)q * 16;
            const uint32_t* src = (tile ? g_Bl : g_Bh)
                                  + (size_t)(n0 + row) * 512 + kcu + q * 4;
            cp_async16(dst, src);
        }
    };

    stageA(0);
    loadB(0, 0);
    CP_COMMIT();
    convertA(0);
    stageA(1);
    CP_WAIT(0);
    __syncthreads();

    for (int c = 0; c < 32; c++) {
        const uint32_t base = (uint32_t)(c & 1) * BUFSZ;
        const uint32_t nbase = (uint32_t)((c + 1) & 1) * BUFSZ;
        if (c < 31) {
            loadB(c + 1, nbase);
            CP_COMMIT();
        }
        #pragma unroll
        for (int kk = 0; kk < 2; kk++) {
            uint32_t ah[2][4], al[2][4], bf[4];
            #pragma unroll
            for (int mi = 0; mi < 2; mi++)
                ldmx4(ah[mi], sb + base + a_rel + (uint32_t)(mi * 16) * TPITCH + kk * 32);
            #pragma unroll
            for (int mi = 0; mi < 2; mi++)
                ldmx4(al[mi], sb + base + TSZ + a_rel + (uint32_t)(mi * 16) * TPITCH + kk * 32);
            #pragma unroll
            for (int np = 0; np < 4; np++) {
                ldmx4(bf, sb + base + 2 * TSZ + b_rel + (uint32_t)(np * 16) * TPITCH + kk * 32);
                #pragma unroll
                for (int mi = 0; mi < 2; mi++)
                    #pragma unroll
                    for (int nb = 0; nb < 2; nb++)
                        mma_bf16(acc[mi][np * 2 + nb], ah[mi], bf[nb], bf[nb + 2]);
                #pragma unroll
                for (int mi = 0; mi < 2; mi++)
                    #pragma unroll
                    for (int nb = 0; nb < 2; nb++)
                        mma_bf16(acc[mi][np * 2 + nb], al[mi], bf[nb], bf[nb + 2]);
            }
            #pragma unroll
            for (int np = 0; np < 4; np++) {
                ldmx4(bf, sb + base + 3 * TSZ + b_rel + (uint32_t)(np * 16) * TPITCH + kk * 32);
                #pragma unroll
                for (int mi = 0; mi < 2; mi++)
                    #pragma unroll
                    for (int nb = 0; nb < 2; nb++)
                        mma_bf16(acc[mi][np * 2 + nb], ah[mi], bf[nb], bf[nb + 2]);
            }
        }
        if (c < 31) {
            convertA(nbase);
            if (c < 30) stageA(c + 2);
            CP_WAIT(0);
        }
        __syncthreads();
    }

    #pragma unroll
    for (int mi = 0; mi < 2; mi++) {
        const int r = m0 + wm * 32 + mi * 16 + (lane >> 2);
        #pragma unroll
        for (int ni = 0; ni < 8; ni++) {
            const int cc = n0 + wn * 64 + ni * 8 + (lane & 3) * 2;
            const float b0 = bd[cc], b1 = bd[cc + 1];
            float2 v0 = make_float2(acc[mi][ni][0] + b0, acc[mi][ni][1] + b1);
            float2 v1 = make_float2(acc[mi][ni][2] + b0, acc[mi][ni][3] + b1);
            *reinterpret_cast<float2*>(C + (size_t)r * 512 + cc) = v0;
            *reinterpret_cast<float2*>(C + (size_t)(r + 8) * 512 + cc) = v1;
        }
    }
}

// -------------------------------------------------------------------------
// Gates via mma (unchanged from R14 win). GTP=80 (16B-aligned rows).
#define GTP 80
#define GTSZ (128 * GTP)
#define GBUF (4 * GTSZ)
#define SMEM_G (2 * GBUF)   // 81920 B

__global__ __launch_bounds__(256, 2) void k_gates_mma() {
    extern __shared__ char smg[];
    const int tid = threadIdx.x;
    const int lane = tid & 31, warp = tid >> 5;
    const int wm = warp >> 1, wn = warp & 1;
    const int j0 = blockIdx.x * 128;
    const int ks = blockIdx.y;
    const uint32_t sb = smem_u32(smg);

    float acc[2][8][4];
    #pragma unroll
    for (int i = 0; i < 2; i++)
        #pragma unroll
        for (int j = 0; j < 8; j++)
            #pragma unroll
            for (int k = 0; k < 4; k++) acc[i][j][k] = 0.f;

    const uint32_t a_rel = (uint32_t)(wm * 32 + (lane & 15)) * GTP + ((lane >> 4) * 8) * 2;
    const uint32_t b_rel = (uint32_t)(wn * 64 + (lane & 15)) * GTP + ((lane >> 4) * 8) * 2;
    const int koff = ks * 192;

    auto loadT = [&](int c, uint32_t base) {
        const int kc = koff + c * 32;
        #pragma unroll
        for (int i = 0; i < 8; i++) {
            const int t = tid + i * 256;
            const int tile = t >> 9;             // 0 Wh, 1 Wl, 2 xh, 3 xl
            const int tt = t & 511;
            const int row = tt >> 2, q = tt & 3;
            const uint32_t dst = sb + base + (uint32_t)tile * GTSZ
                                 + (uint32_t)row * GTP + (uint32_t)q * 16;
            const __nv_bfloat16* src;
            if (tile == 0)      src = g_Wuh + (size_t)(j0 + row) * GK + kc + q * 8;
            else if (tile == 1) src = g_Wul + (size_t)(j0 + row) * GK + kc + q * 8;
            else if (tile == 2) src = g_xbh + (size_t)row * GK + kc + q * 8;
            else                src = g_xbl + (size_t)row * GK + kc + q * 8;
            cp_async16(dst, src);
        }
    };

    loadT(0, 0);
    CP_COMMIT();
    CP_WAIT(0);
    __syncthreads();

    for (int c = 0; c < 6; c++) {
        const uint32_t base = (uint32_t)(c & 1) * GBUF;
        const uint32_t nbase = (uint32_t)((c + 1) & 1) * GBUF;
        if (c < 5) {
            loadT(c + 1, nbase);
            CP_COMMIT();
        }
        #pragma unroll
        for (int kk = 0; kk < 2; kk++) {
            uint32_t ah[2][4], al[2][4], bf[4];
            #pragma unroll
            for (int mi = 0; mi < 2; mi++)
                ldmx4(ah[mi], sb + base + a_rel + (uint32_t)(mi * 16) * GTP + kk * 32);
            #pragma unroll
            for (int mi = 0; mi < 2; mi++)
                ldmx4(al[mi], sb + base + GTSZ + a_rel + (uint32_t)(mi * 16) * GTP + kk * 32);
            #pragma unroll
            for (int np = 0; np < 4; np++) {
                ldmx4(bf, sb + base + 2 * GTSZ + b_rel + (uint32_t)(np * 16) * GTP + kk * 32);
                #pragma unroll
                for (int mi = 0; mi < 2; mi++)
                    #pragma unroll
                    for (int nb = 0; nb < 2; nb++)
                        mma_bf16(acc[mi][np * 2 + nb], ah[mi], bf[nb], bf[nb + 2]);
                #pragma unroll
                for (int mi = 0; mi < 2; mi++)
                    #pragma unroll
                    for (int nb = 0; nb < 2; nb++)
                        mma_bf16(acc[mi][np * 2 + nb], al[mi], bf[nb], bf[nb + 2]);
            }
            #pragma unroll
            for (int np = 0; np < 4; np++) {
                ldmx4(bf, sb + base + 3 * GTSZ + b_rel + (uint32_t)(np * 16) * GTP + kk * 32);
                #pragma unroll
                for (int mi = 0; mi < 2; mi++)
                    #pragma unroll
                    for (int nb = 0; nb < 2; nb++)
                        mma_bf16(acc[mi][np * 2 + nb], ah[mi], bf[nb], bf[nb + 2]);
            }
        }
        if (c < 5) CP_WAIT(0);
        __syncthreads();
    }

    float* P = g_part + (size_t)ks * 2048 * BB;
    #pragma unroll
    for (int mi = 0; mi < 2; mi++) {
        const int r = j0 + wm * 32 + mi * 16 + (lane >> 2);
        #pragma unroll
        for (int ni = 0; ni < 8; ni++) {
            const int cc = wn * 64 + ni * 8 + (lane & 3) * 2;
            *reinterpret_cast<float2*>(P + (size_t)r * BB + cc) =
                make_float2(acc[mi][ni][0], acc[mi][ni][1]);
            *reinterpret_cast<float2*>(P + (size_t)(r + 8) * BB + cc) =
                make_float2(acc[mi][ni][2], acc[mi][ni][3]);
        }
    }
}

// -------------------------------------------------------------------------
// Small tall-skinny GEMM body (fp32) — used by k_q
template <int JPT>
__device__ __forceinline__ void gemm_cols(const float* __restrict__ W, int K,
                                          int kc0, int kcnt,
                                          const float* __restrict__ xcol,
                                          int b, int jj, float acc[JPT], float* Ws) {
    const int JT = 2 * JPT;
    #pragma unroll
    for (int u = 0; u < JPT; u++) acc[u] = 0.f;
    for (int kc = kc0; kc < kc0 + kcnt; kc += 64) {
        __syncthreads();
        for (int i = threadIdx.x; i < JT * 16; i += blockDim.x) {
            int j = i >> 4, kq = i & 15;
            *reinterpret_cast<float4*>(Ws + j * 64 + kq * 4) =
                *reinterpret_cast<const float4*>(W + (size_t)j * K + kc + kq * 4);
        }
        __syncthreads();
        #pragma unroll 4
        for (int k = 0; k < 64; k += 4) {
            float x0 = xcol[(size_t)(kc + k + 0) * BB + b];
            float x1 = xcol[(size_t)(kc + k + 1) * BB + b];
            float x2 = xcol[(size_t)(kc + k + 2) * BB + b];
            float x3 = xcol[(size_t)(kc + k + 3) * BB + b];
            #pragma unroll
            for (int u = 0; u < JPT; u++) {
                float4 w = *reinterpret_cast<const float4*>(Ws + (jj * JPT + u) * 64 + k);
                acc[u] = fmaf(w.x, x0, acc[u]);
                acc[u] = fmaf(w.y, x1, acc[u]);
                acc[u] = fmaf(w.z, x2, acc[u]);
                acc[u] = fmaf(w.w, x3, acc[u]);
            }
        }
    }
}

// GRU combine: sum partials + biases, h' = (1-z)*n + z*h.
// Writes fp32 h state AND bf16 h/l of h' directly (scattered 2B stores, cheap).
__global__ void k_comb(const float* __restrict__ b_ih, const float* __restrict__ b_hh) {
    int gid = blockIdx.x * blockDim.x + threadIdx.x;
    if (gid >= BB * EH) return;
    int b = gid & 127, e = gid >> 7;
    float rg = b_ih[e] + b_hh[e];
    float zg = b_ih[512 + e] + b_hh[512 + e];
    float xn = b_ih[1024 + e];
    float hn = b_hh[1024 + e];
    #pragma unroll
    for (int ks = 0; ks < NSPLIT; ks++) {
        const float* P = g_part + (size_t)ks * 2048 * BB;
        rg += P[(size_t)e * BB + b];
        zg += P[(size_t)(512 + e) * BB + b];
        xn += P[(size_t)(1024 + e) * BB + b];
        hn += P[(size_t)(1536 + e) * BB + b];
    }
    float hv = g_xT[(size_t)(1024 + e) * BB + b];
    float r = 1.f / (1.f + expf(-rg));
    float z = 1.f / (1.f + expf(-zg));
    float n = tanhf(fmaf(r, hn, xn));
    float hnew = fmaf(1.f - z, n, z * hv);
    g_xT[(size_t)(1024 + e) * BB + b] = hnew;
    __nv_bfloat16 hb = __float2bfloat16_rn(hnew);
    g_xbh[(size_t)b * GK + 1024 + e] = hb;
    g_xbl[(size_t)b * GK + 1024 + e] =
        __float2bfloat16_rn(hnew - __bfloat162float(hb));
}

// q partials: grid (64 jblocks, NSPLIT), K=512
__global__ __launch_bounds__(256) void k_q(const float* __restrict__ wq) {
    __shared__ float Ws[8 * 64];
    const int j0 = blockIdx.x * 8;
    const int ks = blockIdx.y;
    const int tid = threadIdx.x;
    const int b = tid & 127, jj = tid >> 7;
    const int kper = 512 / NSPLIT;
    float acc[4];
    gemm_cols<4>(wq + (size_t)j0 * 512, 512, ks * kper, kper,
                 g_xT + (size_t)1024 * BB, b, jj, acc, Ws);
    float* P = g_qpart + (size_t)ks * BB * AA;
    #pragma unroll
    for (int u = 0; u < 4; u++) {
        int jl = jj * 4 + u;
        P[(size_t)b * 512 + j0 + jl] = acc[u];
    }
}

__global__ void k_qsum(const float* __restrict__ bq) {
    int gid = blockIdx.x * blockDim.x + threadIdx.x;
    if (gid >= BB * AA) return;
    int a = gid & 511;
    float s = bq[a];
    #pragma unroll
    for (int ks = 0; ks < NSPLIT; ks++) s += g_qpart[(size_t)ks * BB * AA + gid];
    g_q[gid] = s;
}

// score[b,l] = ws . tanh(q[b] + d_proj[b,l]) + bs, masked  (3200 blocks)
__global__ __launch_bounds__(256) void k_score(const float* __restrict__ ws,
                                               const float* __restrict__ bsp,
                                               int t, float* __restrict__ outs) {
    const int b = blockIdx.x / 25;
    const int lg = blockIdx.x % 25;
    const int w = threadIdx.x >> 5, lane = threadIdx.x & 31;
    const int l = lg * 8 + w;
    const float4* dp = reinterpret_cast<const float4*>(g_dproj + (size_t)(b * LL + l) * AA);
    const float4* qv = reinterpret_cast<const float4*>(g_q + (size_t)b * AA);
    const float4* wv = reinterpret_cast<const float4*>(ws);
    float acc = 0.f;
    #pragma unroll
    for (int i = 0; i < 4; i++) {
        float4 d = dp[lane + 32 * i];
        float4 q = qv[lane + 32 * i];
        float4 s = wv[lane + 32 * i];
        acc = fmaf(s.x, tanh_fast(d.x + q.x), acc);
        acc = fmaf(s.y, tanh_fast(d.y + q.y), acc);
        acc = fmaf(s.z, tanh_fast(d.z + q.z), acc);
        acc = fmaf(s.w, tanh_fast(d.w + q.w), acc);
    }
    #pragma unroll
    for (int off = 16; off; off >>= 1) acc += __shfl_xor_sync(0xffffffffu, acc, off);
    if (lane == 0) {
        float s = acc + bsp[0];
        for (int tt = 0; tt < t; tt++)
            if (g_idx[b * TT + tt] == l) s = -1000000.0f;
        outs[((size_t)b * TT + t) * LL + l] = s;
    }
}

// argmax per b, record idx, gather selected sentence -> bf16 h/l s_prev rows
__global__ void k_argmax(int t, const float* __restrict__ sent,
                         const float* __restrict__ outs, float* __restrict__ out_sel) {
    const int b = blockIdx.x, tid = threadIdx.x;   // 128 blocks x 256
    const float* sc = outs + ((size_t)b * TT + t) * LL;
    float bv = -3.0e38f; int bi = 0;
    for (int l = tid; l < LL; l += 256) {
        float v = sc[l];
        if (v > bv) { bv = v; bi = l; }
    }
    __shared__ float sv[256]; __shared__ int si[256];
    sv[tid] = bv; si[tid] = bi; __syncthreads();
    for (int s = 128; s > 0; s >>= 1) {
        if (tid < s) {
            if (sv[tid + s] > sv[tid] || (sv[tid + s] == sv[tid] && si[tid + s] < si[tid])) {
                sv[tid] = sv[tid + s]; si[tid] = si[tid + s];
            }
        }
        __syncthreads();
    }
    const int idx = si[0];
    if (tid == 0) { g_idx[b * TT + t] = idx; out_sel[b * TT + t] = (float)idx; }
    // gather selected sentence as bf16 h/l (k < 1024; 4 floats per thread)
    const float* srow = sent + ((size_t)(b * LL) + idx) * D2;
    const int k = tid * 4;
    float4 v = *reinterpret_cast<const float4*>(srow + k);
    uint32_t h0 = pkbf(v.x, v.y), h1 = pkbf(v.z, v.w);
    uint32_t l0 = pkbf(v.x - bf_lo(h0), v.y - bf_hi(h0));
    uint32_t l1 = pkbf(v.z - bf_lo(h1), v.w - bf_hi(h1));
    size_t off = (size_t)b * GK + k;
    *reinterpret_cast<uint2*>(g_xbh + off) = make_uint2(h0, h1);
    *reinterpret_cast<uint2*>(g_xbl + off) = make_uint2(l0, l1);
}

// -------------------------------------------------------------------------
extern "C" void kernel_launch(void* const* d_in, const int* in_sizes, int n_in,
                              void* d_out, int out_size) {
    const float* sent = (const float*)d_in[0];
    const float* h0w  = (const float*)d_in[1];
    const float* h0b  = (const float*)d_in[2];
    const float* w_ih = (const float*)d_in[3];
    const float* w_hh = (const float*)d_in[4];
    const float* b_ih = (const float*)d_in[5];
    const float* b_hh = (const float*)d_in[6];
    const float* wq   = (const float*)d_in[7];
    const float* bq   = (const float*)d_in[8];
    const float* wd   = (const float*)d_in[9];
    const float* bd   = (const float*)d_in[10];
    const float* ws   = (const float*)d_in[11];
    const float* bsp  = (const float*)d_in[12];
    (void)in_sizes; (void)n_in; (void)out_size;

    float* out = (float*)d_out;
    float* out_scores = out;
    float* out_sel = out + (size_t)BB * TT * LL;

    float* dproj_ptr = nullptr;
    cudaGetSymbolAddress((void**)&dproj_ptr, g_dproj);

    cudaFuncSetAttribute(k_dproj, cudaFuncAttributeMaxDynamicSharedMemorySize, SMEM_DP);
    cudaFuncSetAttribute(k_gates_mma, cudaFuncAttributeMaxDynamicSharedMemorySize, SMEM_G);

    k_cvtW<<<GM, 256>>>(w_ih, w_hh);
    k_cvtB<<<512, 256>>>(wd);
    k_init<<<BB, 256>>>(sent, h0w, h0b);
    k_dproj<<<dim3(4, 200), 256, SMEM_DP>>>(sent, bd, dproj_ptr);
    for (int t = 0; t < TT; t++) {
        k_gates_mma<<<dim3(16, 8), 256, SMEM_G>>>();
        k_comb<<<256, 256>>>(b_ih, b_hh);
        k_q<<<dim3(64, NSPLIT), 256>>>(wq);
        k_qsum<<<256, 256>>>(bq);
        k_score<<<BB * 25, 256>>>(ws, bsp, t, out_scores);
        k_argmax<<<BB, 256>>>(t, sent, out_scores, out_sel);
    }
}